// round 13
// baseline (speedup 1.0000x reference)
#include <cuda_runtime.h>

// result = 2*(C-1)/C^2 * mean(|ct|)  with C=8, H=W=512.
// Per pixel with target t, argmax q, value v:
//   sum_{c,l} |v*[l==t] - v*[c==q]| = 2*(C-1)*|v|, independent of t and q.
// pred_stage1 / target are never read; this is an abs-mean of ct (1 MB).
//
// Latency-chain-optimized single launch:
//  - 64 CTAs x 256 thr, 4 independent float4 loads per thread (MLP=4)
//  - warp shfl reduce -> smem -> thread0 flat sum (no 2nd shfl tree)
//  - ONE packed u64 atomicAdd per CTA: bits[56:64)=arrival count,
//    bits[0:56)=2^30 fixed-point sum. Last arriver reads the total from the
//    atomic's return value (no fence, no partials array, no re-read).
//  - integer adds commute exactly -> bit-deterministic across replays.

#define NUM_BLOCKS  64
#define NUM_THREADS 256
#define FP_SCALE    1073741824.0   // 2^30

__device__ unsigned long long g_acc = 0ULL;

__global__ void __launch_bounds__(NUM_THREADS)
abs_mean_onepass(const float4* __restrict__ ct4, float scale,
                 float* __restrict__ out) {
    // 65536 float4s total -> 4 per thread, coalesced, all independent
    int base = blockIdx.x * (NUM_THREADS * 4) + threadIdx.x;
    float4 a = ct4[base];
    float4 b = ct4[base + NUM_THREADS];
    float4 c = ct4[base + 2 * NUM_THREADS];
    float4 d = ct4[base + 3 * NUM_THREADS];

    float s = (fabsf(a.x) + fabsf(a.y)) + (fabsf(a.z) + fabsf(a.w))
            + (fabsf(b.x) + fabsf(b.y)) + (fabsf(b.z) + fabsf(b.w))
            + (fabsf(c.x) + fabsf(c.y)) + (fabsf(c.z) + fabsf(c.w))
            + (fabsf(d.x) + fabsf(d.y)) + (fabsf(d.z) + fabsf(d.w));

    // warp reduce
    #pragma unroll
    for (int o = 16; o > 0; o >>= 1)
        s += __shfl_xor_sync(0xffffffffu, s, o);

    __shared__ float ws[NUM_THREADS / 32];
    if ((threadIdx.x & 31) == 0) ws[threadIdx.x >> 5] = s;
    __syncthreads();

    if (threadIdx.x == 0) {
        // flat 8-way sum: shorter dependency chain than a second shfl tree
        float bs = ((ws[0] + ws[1]) + (ws[2] + ws[3]))
                 + ((ws[4] + ws[5]) + (ws[6] + ws[7]));

        // per-block sum < 2^15 -> fx < 2^45; x64 blocks < 2^51 < 2^56: no
        // carry into the count byte.
        unsigned long long fx =
            (unsigned long long)__double2ll_rn((double)bs * FP_SCALE);
        unsigned long long pkt = (1ULL << 56) | fx;
        unsigned long long old = atomicAdd(&g_acc, pkt);

        if ((old >> 56) == (unsigned long long)(NUM_BLOCKS - 1)) {
            unsigned long long total = (old & ((1ULL << 56) - 1ULL)) + fx;
            out[0] = (float)((double)total * (1.0 / FP_SCALE) * (double)scale);
            g_acc = 0ULL;  // reset for next graph replay
        }
    }
}

extern "C" void kernel_launch(void* const* d_in, const int* in_sizes, int n_in,
                              void* d_out, int out_size) {
    // inputs: [0] pred_stage1 f32 (unused), [1] ct f32, [2] target i64 (unused)
    const float* ct = (const float*)d_in[1];
    int n = in_sizes[1];  // 262144

    const int C = 8;
    float scale = (2.0f * (C - 1)) / ((float)(C * C)) / (float)n;

    abs_mean_onepass<<<NUM_BLOCKS, NUM_THREADS>>>((const float4*)ct, scale,
                                                  (float*)d_out);
}

// round 14
// speedup vs baseline: 2.2407x; 2.2407x over previous
#include <cuda_runtime.h>

// result = 2*(C-1)/C^2 * mean(|ct|)  with C=8, H=W=512.
// Per pixel with target t, argmax q, value v:
//   sum_{c,l} |v*[l==t] - v*[c==q]| = 2*(C-1)*|v|, independent of t and q.
// pred_stage1 / target are never read; this is an abs-mean of ct (1 MB).
//
// Two kernels (best-measured structure), with PDL overlap: stage2 is launched
// with programmatic-stream-serialization so its dispatch overlaps stage1's
// execution; it blocks only at cudaGridDependencySynchronize(). Stage1 blocks
// fire cudaTriggerProgrammaticLaunchCompletion() immediately after publishing
// their partial, releasing stage2 as early as possible.
// Fixed summation order everywhere -> bit-deterministic across replays.

#define S1_BLOCKS  128
#define S1_THREADS 256

__device__ float g_partials[S1_BLOCKS];

__global__ void __launch_bounds__(S1_THREADS)
abs_sum_stage1(const float4* __restrict__ ct4) {
    // 65536 float4s -> 2 per thread, coalesced, independent (MLP=2)
    int base = blockIdx.x * (S1_THREADS * 2) + threadIdx.x;
    float4 a = ct4[base];
    float4 b = ct4[base + S1_THREADS];
    float s = (fabsf(a.x) + fabsf(a.y)) + (fabsf(a.z) + fabsf(a.w))
            + (fabsf(b.x) + fabsf(b.y)) + (fabsf(b.z) + fabsf(b.w));

    #pragma unroll
    for (int o = 16; o > 0; o >>= 1)
        s += __shfl_xor_sync(0xffffffffu, s, o);

    __shared__ float ws[S1_THREADS / 32];
    if ((threadIdx.x & 31) == 0) ws[threadIdx.x >> 5] = s;
    __syncthreads();

    if (threadIdx.x == 0) {
        float bs = ((ws[0] + ws[1]) + (ws[2] + ws[3]))
                 + ((ws[4] + ws[5]) + (ws[6] + ws[7]));
        g_partials[blockIdx.x] = bs;
        __threadfence();
        cudaTriggerProgrammaticLaunchCompletion();
    }
}

__global__ void __launch_bounds__(32)
abs_sum_stage2(float* __restrict__ out, float scale) {
    cudaGridDependencySynchronize();  // wait for all stage1 blocks' triggers

    int t = threadIdx.x;
    // fixed order: deterministic
    float s = (g_partials[t]      + g_partials[t + 32])
            + (g_partials[t + 64] + g_partials[t + 96]);
    #pragma unroll
    for (int o = 16; o > 0; o >>= 1)
        s += __shfl_xor_sync(0xffffffffu, s, o);
    if (t == 0) out[0] = s * scale;
}

extern "C" void kernel_launch(void* const* d_in, const int* in_sizes, int n_in,
                              void* d_out, int out_size) {
    // inputs: [0] pred_stage1 f32 (unused), [1] ct f32, [2] target i64 (unused)
    const float* ct = (const float*)d_in[1];
    int n = in_sizes[1];  // 262144

    const int C = 8;
    float scale = (2.0f * (C - 1)) / ((float)(C * C)) / (float)n;

    abs_sum_stage1<<<S1_BLOCKS, S1_THREADS>>>((const float4*)ct);

    // stage2 with programmatic dependent launch: dispatch overlaps stage1
    cudaLaunchConfig_t cfg = {};
    cfg.gridDim = dim3(1, 1, 1);
    cfg.blockDim = dim3(32, 1, 1);
    cfg.dynamicSmemBytes = 0;
    cfg.stream = 0;
    cudaLaunchAttribute attr[1];
    attr[0].id = cudaLaunchAttributeProgrammaticStreamSerialization;
    attr[0].val.programmaticStreamSerializationAllowed = 1;
    cfg.attrs = attr;
    cfg.numAttrs = 1;
    cudaLaunchKernelEx(&cfg, abs_sum_stage2, (float*)d_out, scale);
}